// round 7
// baseline (speedup 1.0000x reference)
#include <cuda_runtime.h>
#include <math.h>
#include <stdint.h>

// Problem constants
#define BB   256
#define KIN  8
#define CC   1152
#define JJ   10
#define DD   16
#define JD   160
#define XKC  9216          // KIN*CC

#define NCH1 144           // GEMM1 k-chunks (8 capsules x 8 kin = 64 K each)
#define NCH2 72            // GEMM2 r-chunks (16 capsules -> 128 M rows)

// smem layout (float offsets). A tiles 128x64 stride 68; B tiles 64x160 stride 168.
#define AHo  0
#define ALo  8704          // 128*68
#define BHo  17408
#define BLo  28160         // +64*168
#define CSo  38912
#define SMEMF 38992
#define SMEMB (SMEMF * 4)  // 155968 bytes

// ---------------------------------------------------------------------------
// Device globals (runtime allocation forbidden)
// ---------------------------------------------------------------------------
__device__ alignas(16) float g_spart[NCH1 * BB * JD];  // split-K partials (23.6MB)
__device__ alignas(16) float g_xt[XKC * BB];           // x transposed [kc][b]
__device__ alignas(16) float g_v[BB * JD];             // v[b][jd]
__device__ alignas(16) float g_b[CC * JJ];             // routing logits

__device__ __forceinline__ uint32_t tf32r(float f) {
    uint32_t u; asm("cvt.rna.tf32.f32 %0, %1;" : "=r"(u) : "f"(f)); return u;
}
__device__ __forceinline__ void hilo(float v, uint32_t& hi, uint32_t& lo) {
    hi = tf32r(v);
    lo = tf32r(v - __uint_as_float(hi));
}
// m16n8k8 tf32 HMMA, D += A*B (row.col canonical fragment mapping)
__device__ __forceinline__ void mma8(float* d, const uint32_t* a, const uint32_t* b) {
    asm volatile(
        "mma.sync.aligned.m16n8k8.row.col.f32.tf32.tf32.f32 "
        "{%0,%1,%2,%3}, {%4,%5,%6,%7}, {%8,%9}, {%0,%1,%2,%3};"
        : "+f"(d[0]), "+f"(d[1]), "+f"(d[2]), "+f"(d[3])
        : "r"(a[0]), "r"(a[1]), "r"(a[2]), "r"(a[3]), "r"(b[0]), "r"(b[1]));
}

// ---------------------------------------------------------------------------
// Kernel T: transpose x -> g_xt[kc][b] (once per call, for GEMM2's A)
// ---------------------------------------------------------------------------
__global__ void __launch_bounds__(256) kernT(const float* __restrict__ x) {
    __shared__ float ts[32][33];
    int tx = threadIdx.x & 31, ty = threadIdx.x >> 5;
    int kc0 = blockIdx.x * 32, b0 = blockIdx.y * 32;
#pragma unroll
    for (int r = ty; r < 32; r += 8)
        ts[r][tx] = x[(size_t)(b0 + r) * XKC + kc0 + tx];
    __syncthreads();
#pragma unroll
    for (int r = ty; r < 32; r += 8)
        g_xt[(size_t)(kc0 + r) * BB + b0 + tx] = ts[tx][r];
}

// ---------------------------------------------------------------------------
// Shared main loop: M=128 x N=160 x K=64, 8 warps, tf32x3 via mma.sync.
// A in smem [m][k] stride 68 (hi/lo), B in smem [k][n] stride 168 (hi/lo).
// Each warp: m-tile = w*16, all 20 n-tiles. Result left in d[20][4].
// ---------------------------------------------------------------------------
__device__ __forceinline__ void gemm_core(const uint32_t* ah, const uint32_t* al,
                                          const uint32_t* bh, const uint32_t* bl,
                                          int tid, float d[20][4]) {
    int w = tid >> 5, lane = tid & 31, g = lane >> 2, tig = lane & 3;
#pragma unroll
    for (int nt = 0; nt < 20; nt++)
#pragma unroll
        for (int q = 0; q < 4; q++) d[nt][q] = 0.f;

    int ar0 = (w * 16 + g) * 68, ar1 = (w * 16 + g + 8) * 68;
#pragma unroll
    for (int k8 = 0; k8 < 8; k8++) {
        int kc = k8 * 8 + tig;
        uint32_t aH[4] = {ah[ar0 + kc], ah[ar1 + kc], ah[ar0 + kc + 4], ah[ar1 + kc + 4]};
        uint32_t aL[4] = {al[ar0 + kc], al[ar1 + kc], al[ar0 + kc + 4], al[ar1 + kc + 4]};
        int br0 = kc * 168 + g, br1 = (kc + 4) * 168 + g;
#pragma unroll
        for (int nt = 0; nt < 20; nt++) {
            uint32_t bH[2] = {bh[br0 + nt * 8], bh[br1 + nt * 8]};
            uint32_t bL[2] = {bl[br0 + nt * 8], bl[br1 + nt * 8]};
            mma8(d[nt], aH, bH);
            mma8(d[nt], aH, bL);
            mma8(d[nt], aL, bH);
        }
    }
}

// stage the block's 128x160 result into smem base (after a syncthreads)
__device__ __forceinline__ void stage_tile(float* sm, int tid, float d[20][4]) {
    int w = tid >> 5, lane = tid & 31, g = lane >> 2, tig = lane & 3;
#pragma unroll
    for (int nt = 0; nt < 20; nt++) {
        *(float2*)(sm + (w * 16 + g) * JD + nt * 8 + 2 * tig) =
            make_float2(d[nt][0], d[nt][1]);
        *(float2*)(sm + (w * 16 + g + 8) * JD + nt * 8 + 2 * tig) =
            make_float2(d[nt][2], d[nt][3]);
    }
}

// ---------------------------------------------------------------------------
// Kernel B (GEMM1): s_part[chunk][b][jd]; grid (144, 2), block 256
// ---------------------------------------------------------------------------
__global__ void __launch_bounds__(256) kernB(const float* __restrict__ x,
                                             const float* __restrict__ W) {
    extern __shared__ float sm[];
    uint32_t* ah = (uint32_t*)(sm + AHo);
    uint32_t* al = (uint32_t*)(sm + ALo);
    uint32_t* bh = (uint32_t*)(sm + BHo);
    uint32_t* bl = (uint32_t*)(sm + BLo);
    float* cs = sm + CSo;

    int tid = threadIdx.x;
    int c0 = blockIdx.x * 8, b0 = blockIdx.y * 128;

    // per-capsule softmax over J (8 capsules x 10 units)
    if (tid < 80) {
        int cl = tid / 10, j = tid - cl * 10;
        const float* br = g_b + (size_t)(c0 + cl) * JJ;
        float bv[JJ], mx = -1e30f;
#pragma unroll
        for (int q = 0; q < JJ; q++) { bv[q] = br[q]; mx = fmaxf(mx, bv[q]); }
        float sum = 0.f;
#pragma unroll
        for (int q = 0; q < JJ; q++) { bv[q] = expf(bv[q] - mx); sum += bv[q]; }
        cs[tid] = bv[j] / sum;
    }

    // A tile: X[128 m x 64 k], k = kin*8 + cl
    for (int i = tid; i < 8192; i += 256) {
        int m = i >> 6, k = i & 63, kin = k >> 3, cl = k & 7;
        float v = x[(size_t)(b0 + m) * XKC + kin * CC + c0 + cl];
        uint32_t h, l; hilo(v, h, l);
        ah[m * 68 + k] = h; al[m * 68 + k] = l;
    }
    __syncthreads();   // cs ready

    // B tile: P[64 k x 160 n] = c_ij * W
    for (int i = tid; i < 64 * JD; i += 256) {
        int k = i / JD, n = i - k * JD, kin = k >> 3, cl = k & 7;
        float v = cs[cl * 10 + (n >> 4)] *
                  W[(size_t)(c0 + cl) * 1280 + n * 8 + kin];
        uint32_t h, l; hilo(v, h, l);
        bh[k * 168 + n] = h; bl[k * 168 + n] = l;
    }
    __syncthreads();

    float d[20][4];
    gemm_core(ah, al, bh, bl, tid, d);

    __syncthreads();
    stage_tile(sm, tid, d);
    __syncthreads();

    float* dst = g_spart + (size_t)blockIdx.x * (BB * JD) + (size_t)b0 * JD;
    for (int i = tid; i < 128 * JD / 4; i += 256)
        ((float4*)dst)[i] = ((const float4*)sm)[i];
}

// ---------------------------------------------------------------------------
// Kernel C: reduce 144 split-K partials + squash -> g_v ; final iter -> d_out
// ---------------------------------------------------------------------------
__global__ void __launch_bounds__(512) kernC(float* __restrict__ out) {
    int idx = blockIdx.x * 512 + threadIdx.x;   // b*160 + jd
    float s = 1e-5f;                            // ref adds 1e-5 BEFORE magnitudes
    const float* sp = g_spart + idx;
#pragma unroll 8
    for (int ch = 0; ch < NCH1; ch++)
        s += sp[(size_t)ch * (BB * JD)];

    float mag = s * s;
#pragma unroll
    for (int off = 8; off; off >>= 1)
        mag += __shfl_xor_sync(0xffffffffu, mag, off, 16);

    float v = s * (mag / ((1.f + mag) * sqrtf(mag)));
    g_v[idx] = v;
    if (out) out[idx] = v;                      // (B,J,D,1) same linearization
}

// ---------------------------------------------------------------------------
// Kernel D (GEMM2): G[128 r x 160 jd] over a 64-batch slice, then contract
// with W -> atomicAdd into b_ij. grid (72, 4), block 256
// ---------------------------------------------------------------------------
__global__ void __launch_bounds__(256) kernD(const float* __restrict__ W) {
    extern __shared__ float sm[];
    uint32_t* ah = (uint32_t*)(sm + AHo);
    uint32_t* al = (uint32_t*)(sm + ALo);
    uint32_t* bh = (uint32_t*)(sm + BHo);
    uint32_t* bl = (uint32_t*)(sm + BLo);

    int tid = threadIdx.x;
    int c0 = blockIdx.x * 16, b0 = blockIdx.y * 64;

    // A tile: XT[128 r x 64 b], r = kin*16 + cl
    for (int i = tid; i < 8192; i += 256) {
        int r = i >> 6, b = i & 63, kin = r >> 4, cl = r & 15;
        float v = g_xt[(size_t)(kin * CC + c0 + cl) * BB + b0 + b];
        uint32_t h, l; hilo(v, h, l);
        ah[r * 68 + b] = h; al[r * 68 + b] = l;
    }
    // B tile: V[64 b x 160 n] (natural layout)
    for (int i = tid; i < 64 * JD; i += 256) {
        int k = i / JD, n = i - k * JD;
        float v = g_v[(size_t)(b0 + k) * JD + n];
        uint32_t h, l; hilo(v, h, l);
        bh[k * 168 + n] = h; bl[k * 168 + n] = l;
    }
    __syncthreads();

    float d[20][4];
    gemm_core(ah, al, bh, bl, tid, d);

    __syncthreads();
    stage_tile(sm, tid, d);                     // G tile 128x160 at smem base
    __syncthreads();

    // agreement[c,j] = sum_{kin,d} W[c,j,d,kin] * G[(kin*16+cl)][(j*16+d)]
    if (tid < 160) {
        int cl = tid / 10, j = tid - cl * 10;
        const float* wr = W + (size_t)(c0 + cl) * 1280 + j * 128;
        float ag = 0.f;
#pragma unroll
        for (int kin = 0; kin < KIN; kin++)
#pragma unroll
            for (int d2 = 0; d2 < DD; d2++)
                ag = fmaf(wr[d2 * 8 + kin], sm[(kin * 16 + cl) * JD + j * 16 + d2], ag);
        atomicAdd(&g_b[(c0 + cl) * JJ + j], ag);
    }
}

// ---------------------------------------------------------------------------
// Host launcher (graph-capturable)
// ---------------------------------------------------------------------------
extern "C" void kernel_launch(void* const* d_in, const int* in_sizes, int n_in,
                              void* d_out, int out_size) {
    const float* x = (const float*)d_in[0];
    const float* W = (const float*)d_in[1];
    if (in_sizes[0] != BB * XKC) {   // defensive mapping by element count
        x = (const float*)d_in[1];
        W = (const float*)d_in[0];
    }

    cudaFuncSetAttribute(kernB, cudaFuncAttributeMaxDynamicSharedMemorySize, SMEMB);
    cudaFuncSetAttribute(kernD, cudaFuncAttributeMaxDynamicSharedMemorySize, SMEMB);

    void* pb = nullptr;
    cudaGetSymbolAddress(&pb, g_b);
    cudaMemsetAsync(pb, 0, CC * JJ * sizeof(float));   // b_ij = 0 each call

    kernT<<<dim3(XKC / 32, BB / 32), 256>>>(x);        // x -> g_xt

    dim3 gB(NCH1, 2);    // (144, 2)
    dim3 gD(NCH2, 4);    // (72, 4)
    for (int it = 0; it < 4; it++) {
        kernB<<<gB, 256, SMEMB>>>(x, W);                        // tensor GEMM1
        kernC<<<(BB * JD) / 512, 512>>>(it == 3 ? (float*)d_out : nullptr);
        if (it < 3)                                             // iter-4 agreement dead
            kernD<<<gD, 256, SMEMB>>>(W);                       // tensor GEMM2
    }
}